// round 8
// baseline (speedup 1.0000x reference)
#include <cuda_runtime.h>
#include <math.h>

#define T    2048
#define NF   6142     // 3T-2
#define M0C  4094     // 2T-2
#define BATCH 64

// ---------------- device scratch ----------------
__device__ float2 g_tw[512];         // e^{-2pi i k/4096}, k<512
__device__ float2 g_psi[2048];
__device__ float2 g_W[4096];         // FFT(chirp) in (64S + 8lam + r) slot order
__device__ float2 g_UH[4 * 2048];    // Htilde * phaseU
__device__ float  g_A[9 * BATCH * T];
__device__ float  g_B[9 * BATCH * T];

__device__ __forceinline__ float2 cmul(float2 a, float2 b) {
    return make_float2(fmaf(a.x, b.x, -a.y * b.y), fmaf(a.x, b.y, a.y * b.x));
}
__device__ __forceinline__ float2 cmulc(float2 a, float2 b) {  // a * conj(b)
    return make_float2(fmaf(a.x, b.x, a.y * b.y), fmaf(a.y, b.x, -a.x * b.y));
}
__device__ __forceinline__ float2 cadd(float2 a, float2 b) { return make_float2(a.x + b.x, a.y + b.y); }
__device__ __forceinline__ float2 csub(float2 a, float2 b) { return make_float2(a.x - b.x, a.y - b.y); }
__device__ __forceinline__ int PAD(int e) { return e + (e >> 3) + (e >> 6); }

#define RC8 0.70710678118654752440f

__device__ __forceinline__ void fwd8(float2* a) {
    float2 F0=cadd(a[0],a[4]), F1=csub(a[0],a[4]);
    float2 G0=cadd(a[2],a[6]), G1=csub(a[2],a[6]);
    float2 H0=cadd(a[1],a[5]), H1=csub(a[1],a[5]);
    float2 K0=cadd(a[3],a[7]), K1=csub(a[3],a[7]);
    float2 E0=cadd(F0,G0), E2=csub(F0,G0);
    float2 E1=make_float2(F1.x+G1.y, F1.y-G1.x);
    float2 E3=make_float2(F1.x-G1.y, F1.y+G1.x);
    float2 O0=cadd(H0,K0), O2=csub(H0,K0);
    float2 O1=make_float2(H1.x+K1.y, H1.y-K1.x);
    float2 O3=make_float2(H1.x-K1.y, H1.y+K1.x);
    float2 t1=make_float2(RC8*(O1.x+O1.y),  RC8*(O1.y-O1.x));
    float2 t2=make_float2(O2.y, -O2.x);
    float2 t3=make_float2(RC8*(O3.y-O3.x), -RC8*(O3.x+O3.y));
    a[0]=cadd(E0,O0); a[4]=csub(E0,O0);
    a[1]=cadd(E1,t1); a[5]=csub(E1,t1);
    a[2]=cadd(E2,t2); a[6]=csub(E2,t2);
    a[3]=cadd(E3,t3); a[7]=csub(E3,t3);
}

__device__ __forceinline__ void inv8(float2* a) {
    float2 F0=cadd(a[0],a[4]), F1=csub(a[0],a[4]);
    float2 G0=cadd(a[2],a[6]), G1=csub(a[2],a[6]);
    float2 H0=cadd(a[1],a[5]), H1=csub(a[1],a[5]);
    float2 K0=cadd(a[3],a[7]), K1=csub(a[3],a[7]);
    float2 E0=cadd(F0,G0), E2=csub(F0,G0);
    float2 E1=make_float2(F1.x-G1.y, F1.y+G1.x);
    float2 E3=make_float2(F1.x+G1.y, F1.y-G1.x);
    float2 O0=cadd(H0,K0), O2=csub(H0,K0);
    float2 O1=make_float2(H1.x-K1.y, H1.y+K1.x);
    float2 O3=make_float2(H1.x+K1.y, H1.y-K1.x);
    float2 t1=make_float2(RC8*(O1.x-O1.y),  RC8*(O1.x+O1.y));
    float2 t2=make_float2(-O2.y, O2.x);
    float2 t3=make_float2(-RC8*(O3.x+O3.y), RC8*(O3.x-O3.y));
    a[0]=cadd(E0,O0); a[4]=csub(E0,O0);
    a[1]=cadd(E1,t1); a[5]=csub(E1,t1);
    a[2]=cadd(E2,t2); a[6]=csub(E2,t2);
    a[3]=cadd(E3,t3); a[7]=csub(E3,t3);
}

__device__ __forceinline__ void fwd8h(float2* a) {  // a[4..7] implied zero
    float2 a0=a[0], a1=a[1], a2=a[2], a3=a[3];
    float2 E0=cadd(a0,a2), E2=csub(a0,a2);
    float2 E1=make_float2(a0.x+a2.y, a0.y-a2.x);
    float2 E3=make_float2(a0.x-a2.y, a0.y+a2.x);
    float2 O0=cadd(a1,a3), O2=csub(a1,a3);
    float2 O1=make_float2(a1.x+a3.y, a1.y-a3.x);
    float2 O3=make_float2(a1.x-a3.y, a1.y+a3.x);
    float2 t1=make_float2(RC8*(O1.x+O1.y),  RC8*(O1.y-O1.x));
    float2 t2=make_float2(O2.y, -O2.x);
    float2 t3=make_float2(RC8*(O3.y-O3.x), -RC8*(O3.x+O3.y));
    a[0]=cadd(E0,O0); a[4]=csub(E0,O0);
    a[1]=cadd(E1,t1); a[5]=csub(E1,t1);
    a[2]=cadd(E2,t2); a[6]=csub(E2,t2);
    a[3]=cadd(E3,t3); a[7]=csub(E3,t3);
}

__device__ __forceinline__ void twid_fwd(float2* y, float2 w1) {
    float2 w2=cmul(w1,w1), w3=cmul(w2,w1), w4=cmul(w2,w2);
    float2 w5=cmul(w3,w2), w6=cmul(w3,w3), w7=cmul(w4,w3);
    y[1]=cmul(y[1],w1); y[2]=cmul(y[2],w2); y[3]=cmul(y[3],w3); y[4]=cmul(y[4],w4);
    y[5]=cmul(y[5],w5); y[6]=cmul(y[6],w6); y[7]=cmul(y[7],w7);
}
__device__ __forceinline__ void twid_inv(float2* y, float2 w1) {
    float2 w2=cmul(w1,w1), w3=cmul(w2,w1), w4=cmul(w2,w2);
    float2 w5=cmul(w3,w2), w6=cmul(w3,w3), w7=cmul(w4,w3);
    y[1]=cmulc(y[1],w1); y[2]=cmulc(y[2],w2); y[3]=cmulc(y[3],w3); y[4]=cmulc(y[4],w4);
    y[5]=cmulc(y[5],w5); y[6]=cmulc(y[6],w6); y[7]=cmulc(y[7],w7);
}

// 8x8 (lane-in-group x register) transpose via shfl_xor butterflies (lane bits 0..2).
__device__ __forceinline__ void transpose8(float2* a, int lane) {
#pragma unroll
    for (int b = 1; b < 8; b <<= 1) {
        bool hi = (lane & b) != 0;
#pragma unroll
        for (int jl = 0; jl < 8; jl++) {
            if (jl & b) continue;
            int jh = jl | b;
            float2 send = hi ? a[jl] : a[jh];
            float2 recv;
            recv.x = __shfl_xor_sync(0xffffffffu, send.x, b);
            recv.y = __shfl_xor_sync(0xffffffffu, send.y, b);
            if (hi) a[jl] = recv; else a[jh] = recv;
        }
    }
}

// warp-local 64-point DFT (8-lane groups): in a[r]=c[lam+8r], out (lam,r) <-> k=8r+lam
__device__ __forceinline__ void fwd64(float2* a, int lam, const float2* s_t64) {
    fwd8(a); twid_fwd(a, s_t64[lam]); transpose8(a, lam); fwd8(a);
}
__device__ __forceinline__ void inv64(float2* a, int lam, const float2* s_t64) {
    inv8(a); transpose8(a, lam); twid_inv(a, s_t64[lam]); inv8(a);
}

// ---------------- 3x3 helpers ----------------
__device__ __forceinline__ void rod(float vx, float vy, float vz, float* M) {
    float t2 = vx * vx + vy * vy + vz * vz;
    float th = sqrtf(t2);
    float a, bb;
    if (t2 < 1e-8f) { a = 1.0f - t2 * (1.0f / 6.0f); bb = 0.5f - t2 * (1.0f / 24.0f); }
    else { a = sinf(th) / th; float sh = sinf(0.5f * th); bb = 2.0f * sh * sh / t2; }
    float ct = 1.0f - bb * t2;
    M[0] = ct + bb * vx * vx; M[1] = bb * vx * vy - a * vz; M[2] = bb * vx * vz + a * vy;
    M[3] = bb * vy * vx + a * vz; M[4] = ct + bb * vy * vy; M[5] = bb * vy * vz - a * vx;
    M[6] = bb * vz * vx - a * vy; M[7] = bb * vz * vy + a * vx; M[8] = ct + bb * vz * vz;
}
__device__ __forceinline__ void mm3(const float* A, const float* B, float* C) {
    float t[9];
#pragma unroll
    for (int i = 0; i < 3; i++)
#pragma unroll
        for (int j = 0; j < 3; j++)
            t[3 * i + j] = A[3 * i] * B[j] + A[3 * i + 1] * B[3 + j] + A[3 * i + 2] * B[6 + j];
#pragma unroll
    for (int k = 0; k < 9; k++) C[k] = t[k];
}
__device__ __forceinline__ void inv3(const float* A, float* B) {
    float c00 = A[4] * A[8] - A[5] * A[7];
    float c01 = A[5] * A[6] - A[3] * A[8];
    float c02 = A[3] * A[7] - A[4] * A[6];
    float id = 1.0f / (A[0] * c00 + A[1] * c01 + A[2] * c02);
    B[0] = c00 * id; B[1] = (A[2] * A[7] - A[1] * A[8]) * id; B[2] = (A[1] * A[5] - A[2] * A[4]) * id;
    B[3] = c01 * id; B[4] = (A[0] * A[8] - A[2] * A[6]) * id; B[5] = (A[2] * A[3] - A[0] * A[5]) * id;
    B[6] = c02 * id; B[7] = (A[1] * A[6] - A[0] * A[7]) * id; B[8] = (A[0] * A[4] - A[1] * A[3]) * id;
}

struct FnnW { const float *w1, *b1, *w2, *b2; };

extern __shared__ float2 smem_c[];

// ================= fused precompute kernel =================
__global__ __launch_bounds__(512) void k_pre(
    const float* __restrict__ xd, const float* __restrict__ A1, const float* __restrict__ A2,
    FnnW wf, FnnW wg, FnnW wfp, FnnW wgp)
{
    int blk = blockIdx.x, tid = threadIdx.x;

    if (blk < 64) {
        float* sP = (float*)smem_c;        // 256*9
        float* sv = sP + 2304;             // 6
        int b = blk;
        if (tid == 0) {
            sv[0] = A1[7] - A1[5]; sv[1] = A1[2] - A1[6]; sv[2] = A1[3] - A1[1];
            sv[3] = A2[7] - A2[5]; sv[4] = A2[2] - A2[6]; sv[5] = A2[3] - A2[1];
        }
        __syncthreads();
        float v1x = sv[0], v1y = sv[1], v1z = sv[2], v2x = sv[3], v2y = sv[4], v2z = sv[5];
        bool act = tid < 256;
        float mine[9];
        int t0 = tid * 8;
        if (act) {
            float P[9] = {1, 0, 0, 0, 1, 0, 0, 0, 1};
            for (int tt = 0; tt < 8; tt++) {
                int t = t0 + tt;
                if (t == 0) continue;
                float z1 = xd[(b * T + t) * 2], z2 = xd[(b * T + t) * 2 + 1];
                float M[9];
                rod(z1 * v1x + z2 * v2x, z1 * v1y + z2 * v2y, z1 * v1z + z2 * v2z, M);
                mm3(P, M, P);
            }
#pragma unroll
            for (int k = 0; k < 9; k++) { mine[k] = P[k]; sP[tid * 9 + k] = P[k]; }
        }
        __syncthreads();
        for (int off = 1; off < 256; off <<= 1) {
            float Lm[9];
            bool a2 = act && tid >= off;
            if (a2)
#pragma unroll
                for (int k = 0; k < 9; k++) Lm[k] = sP[(tid - off) * 9 + k];
            __syncthreads();
            if (a2) {
                mm3(Lm, mine, mine);
#pragma unroll
                for (int k = 0; k < 9; k++) sP[tid * 9 + k] = mine[k];
            }
            __syncthreads();
        }
        if (act) {
            float X[9] = {1, 0, 0, 0, 1, 0, 0, 0, 1};
            if (tid > 0)
#pragma unroll
                for (int k = 0; k < 9; k++) X[k] = sP[(tid - 1) * 9 + k];
            for (int tt = 0; tt < 8; tt++) {
                int t = t0 + tt;
                if (t != 0) {
                    float z1 = xd[(b * T + t) * 2], z2 = xd[(b * T + t) * 2 + 1];
                    float M[9];
                    rod(z1 * v1x + z2 * v2x, z1 * v1y + z2 * v2y, z1 * v1z + z2 * v2z, M);
                    mm3(X, M, X);
                }
                float Bi[9];
                inv3(X, Bi);
#pragma unroll
                for (int c = 0; c < 9; c++) {
                    g_A[(c * BATCH + b) * T + t] = X[c];
                    g_B[(c * BATCH + b) * T + t] = Bi[c];
                }
            }
        }
    } else if (blk < 68) {
        int i = (blk - 64) * 512 + tid;
        float s, c;
        if (i < 512) {
            sincospif((float)i / 2048.0f, &s, &c);
            g_tw[i] = make_float2(c, -s);
        }
        long long j = i;
        long long e2 = (2LL * (T - 1) * (M0C + j) + j * j) % NF;
        sincospif(2.0f * (float)e2 / (float)NF, &s, &c);
        g_psi[i] = make_float2(c, s);
    } else if (blk == 68) {
        // ---------------- W role: same 64x64 pipeline as k_main forward ----------------
        float2* s_tw  = smem_c;              // 512
        float2* s_buf = smem_c + 512;        // 4670
        float2* s_t64 = smem_c + 512 + 4670; // 8
        int t = tid;
        {
            float s, c;
            sincospif((float)t / 2048.0f, &s, &c);
            s_tw[t] = make_float2(c, -s);
        }
        __syncthreads();
        if (t < 8) s_t64[t] = s_tw[64 * t];
        __syncthreads();
        int lam = t & 7, S = t >> 3;
        float2 a[8];
#pragma unroll
        for (int r = 0; r < 8; r++) {
            int n = 64 * (lam + 8 * r) + S;
            float2 v;
            if (n == 2048) v = make_float2(0.f, 0.f);
            else {
                long long k = (n < 2048) ? n : (4096 - n);
                long long idx = (k * k) % (2LL * NF);
                float s, c;
                sincospif((float)idx / (float)NF, &s, &c);
                v = make_float2(c, -s);
            }
            a[r] = v;
        }
        fwd64(a, lam, s_t64);
        {
            float2 w0 = s_tw[S * lam];
#pragma unroll
            for (int r = 0; r < 8; r++) a[r] = cmul(a[r], w0);
            twid_fwd(a, s_tw[8 * S]);
        }
#pragma unroll
        for (int r = 0; r < 8; r++) s_buf[PAD(512 * r + 64 * lam + S)] = a[r];
        __syncthreads();
#pragma unroll
        for (int r = 0; r < 8; r++) a[r] = s_buf[PAD(64 * S + 8 * r + lam)];
        fwd64(a, lam, s_t64);
#pragma unroll
        for (int r = 0; r < 8; r++) g_W[64 * S + 8 * lam + r] = a[r];
    } else {
        // ---------------- H role: 128 blocks, 64 j per block, 4 j per warp ----------------
        float* s_q = (float*)smem_c;   // 2048 floats
        int hb = blk - 69;             // 0..127
        int q = hb >> 5;               // 32 blocks per filter
        int jbase = (hb & 31) << 6;    // 64 j's per block
        FnnW W = (q == 0) ? wf : (q == 1) ? wg : (q == 2) ? wfp : wgp;
        for (int p = tid; p < 2048; p += 512) {
            float x = (q == 0 || q == 2) ? (float)(T - 1 - p) : (float)p;
            float z = W.b2[0];
#pragma unroll
            for (int h = 0; h < 5; h++)
                z += W.w2[h] * tanhf(W.w1[h] * x + W.b1[h]);
            s_q[p] = z * expf(-5.0f * x);
        }
        __syncthreads();
        int warp = tid >> 5, lane = tid & 31;
        float2 ph[4], st[4], acc[4];
#pragma unroll
        for (int u = 0; u < 4; u++) {
            int j = jbase + 4 * warp + u;
            long long base = j + (T - 1);
            long long idx0 = (base * (long long)(lane + T - 1)) % NF;
            float s, c;
            sincospif(2.0f * (float)idx0 / (float)NF, &s, &c);
            ph[u] = make_float2(c, -s);
            long long idxs = (base * 32LL) % NF;
            sincospif(2.0f * (float)idxs / (float)NF, &s, &c);
            st[u] = make_float2(c, -s);
            acc[u] = make_float2(0.f, 0.f);
        }
#pragma unroll 4
        for (int it = 0; it < 64; it++) {
            float v = s_q[lane + 32 * it];
#pragma unroll
            for (int u = 0; u < 4; u++) {
                acc[u].x = fmaf(v, ph[u].x, acc[u].x);
                acc[u].y = fmaf(v, ph[u].y, acc[u].y);
                ph[u] = cmul(ph[u], st[u]);
            }
        }
#pragma unroll
        for (int u = 0; u < 4; u++) {
            for (int off = 16; off; off >>= 1) {
                acc[u].x += __shfl_down_sync(0xffffffffu, acc[u].x, off);
                acc[u].y += __shfl_down_sync(0xffffffffu, acc[u].y, off);
            }
        }
        if (lane == 0) {
#pragma unroll
            for (int u = 0; u < 4; u++) {
                int j = jbase + 4 * warp + u;
                long long idxU = (2LL * j * M0C + (long long)j * j) % (2LL * NF);
                float s, c;
                sincospif((float)idxU / (float)NF, &s, &c);
                g_UH[q * 2048 + j] = cmul(acc[u], make_float2(c, s));
            }
        }
    }
}

// ================= main kernel: 64x64 CT, 2 exchanges/round =================
// smem: tw 512 | Z 2334 | E1 4670 | E2 4670 | t512 64 | t64 8 | t256 32 | t32 4 = 12294 f2
#define SMEM_MAIN_F2 (512 + 2334 + 4670 + 4670 + 64 + 8 + 32 + 4)

__global__ __launch_bounds__(512, 2) void k_main(float* __restrict__ out) {
    float2* s_tw   = smem_c;            // 512
    float2* s_Z    = smem_c + 512;      // 2334 (padded 2048)
    float2* sE1    = smem_c + 2846;     // 4670
    float2* sE2    = sE1 + 4670;        // 4670
    float2* s_t512 = sE2 + 4670;        // 64
    float2* s_t64  = s_t512 + 64;       // 8
    float2* s_t256 = s_t64 + 8;         // 32
    float2* s_t32  = s_t256 + 32;       // 4

    int b = blockIdx.x / 9, c = blockIdx.x % 9;
    int t = threadIdx.x;

    s_tw[t] = g_tw[t & 511];
    if (t < 64) s_t512[t] = g_tw[8 * t];
    if (t < 8)  s_t64[t]  = g_tw[64 * t];
    if (t < 32) s_t256[t] = g_tw[16 * t];
    if (t < 4)  s_t32[t]  = g_tw[128 * t];
    __syncthreads();

    const float* Ar = g_A + (c * BATCH + b) * T;
    const float* Ai = g_B + (c * BATCH + b) * T;

    // ===== phase 0: packed 2048-point FFT (256 active threads, ping-pong E1/E2) =====
    float2 a[8];
    if (t < 256) {
#pragma unroll
        for (int j = 0; j < 8; j++) {
            int i = t + 256 * j;
            a[j] = make_float2(Ai[i], Ar[i]);   // z = Xir + i*Xr
        }
        fwd8(a); twid_fwd(a, s_tw[2 * t]);
#pragma unroll
        for (int r = 0; r < 8; r++) sE1[PAD(256 * r + t)] = a[r];
    }
    __syncthreads();
    if (t < 256) {  // stage2: S=256 q=32  E1->E2
        int pb = 256 * (t >> 5), pk = t & 31;
#pragma unroll
        for (int j = 0; j < 8; j++) a[j] = sE1[PAD(pb + pk + 32 * j)];
        fwd8(a); twid_fwd(a, s_t256[pk]);
#pragma unroll
        for (int r = 0; r < 8; r++) sE2[PAD(pb + 32 * r + pk)] = a[r];
    }
    __syncthreads();
    if (t < 256) {  // stage3: S=32 q=4  E2->E1
        int pb = 32 * (t >> 2), pk = t & 3;
#pragma unroll
        for (int j = 0; j < 8; j++) a[j] = sE2[PAD(pb + pk + 4 * j)];
        fwd8(a); twid_fwd(a, s_t32[pk]);
#pragma unroll
        for (int r = 0; r < 8; r++) sE1[PAD(pb + 4 * r + pk)] = a[r];
    }
    __syncthreads();
    if (t < 256) {  // stage4: radix-4 x2, unscramble  E1->s_Z (padded)
#pragma unroll
        for (int h = 0; h < 2; h++) {
            int B = 2 * t + h;
            float2 b4[4];
#pragma unroll
            for (int j = 0; j < 4; j++) b4[j] = sE1[PAD(4 * B + j)];
            float2 e0 = cadd(b4[0], b4[2]), e1 = csub(b4[0], b4[2]);
            float2 o0 = cadd(b4[1], b4[3]), o1 = csub(b4[1], b4[3]);
            float2 y0 = cadd(e0, o0), y2 = csub(e0, o0);
            float2 y1 = make_float2(e1.x + o1.y, e1.y - o1.x);
            float2 y3 = make_float2(e1.x - o1.y, e1.y + o1.x);
            int f = (B >> 6) + 8 * ((B >> 3) & 7) + 64 * (B & 7);
            s_Z[PAD(f)] = y0; s_Z[PAD(f + 512)] = y1;
            s_Z[PAD(f + 1024)] = y2; s_Z[PAD(f + 1536)] = y3;
        }
    }
    __syncthreads();

    // ===== chirp rounds (64x64 Cooley-Tukey) =====
    float2 c1r[4], Pr[4];
    const float sc = 1.0f / (4096.0f * (float)NF);
    const int lam = t & 7;     // lane within 8-group
    const int S   = t >> 3;    // sequence index (step1: j) / k1 (middle)
    const float2 w64l = s_t64[lam];
    const float2 wS0  = s_tw[S * lam];   // w4096^{S*lam}
    const float2 wS1  = s_tw[8 * S];     // w4096^{8S}

#pragma unroll
    for (int s = 0; s < 4; s++) {
        bool useIr = (s == 0 || s == 2);
        const float2* UH = g_UH + s * 2048;

        // ---- step1: gen u (half-zero), warp-local DFT64 over i, outer twiddle ----
#pragma unroll
        for (int r = 0; r < 4; r++) {
            int e = 64 * lam + 512 * r + S;          // e < 2048
            float2 Zj = s_Z[PAD(e)];
            float2 Zm = s_Z[PAD((2048 - e) & 2047)];
            float2 X = useIr
                ? make_float2(0.5f * (Zj.x + Zm.x), 0.5f * (Zj.y - Zm.y))
                : make_float2(0.5f * (Zj.y + Zm.y), 0.5f * (Zm.x - Zj.x));
            a[r] = cmul(X, UH[e]);
        }
        fwd8h(a); twid_fwd(a, w64l); transpose8(a, lam); fwd8(a);
        {
#pragma unroll
            for (int r = 0; r < 8; r++) a[r] = cmul(a[r], wS0);
            twid_fwd(a, wS1);
        }
#pragma unroll
        for (int r = 0; r < 8; r++) sE1[PAD(512 * r + 64 * lam + S)] = a[r];
        __syncthreads();

        // ---- middle: DFT64 over j + W + invDFT64 + conj outer twiddle (registers) ----
#pragma unroll
        for (int r = 0; r < 8; r++) a[r] = sE1[PAD(64 * S + 8 * r + lam)];
        fwd64(a, lam, s_t64);
        {
            const float4* W4 = (const float4*)(g_W + 64 * S + 8 * lam);
            float4 w = W4[0];
            a[0] = cmul(a[0], make_float2(w.x, w.y)); a[1] = cmul(a[1], make_float2(w.z, w.w));
            w = W4[1];
            a[2] = cmul(a[2], make_float2(w.x, w.y)); a[3] = cmul(a[3], make_float2(w.z, w.w));
            w = W4[2];
            a[4] = cmul(a[4], make_float2(w.x, w.y)); a[5] = cmul(a[5], make_float2(w.z, w.w));
            w = W4[3];
            a[6] = cmul(a[6], make_float2(w.x, w.y)); a[7] = cmul(a[7], make_float2(w.z, w.w));
        }
        inv64(a, lam, s_t64);
        {
#pragma unroll
            for (int r = 0; r < 8; r++) a[r] = cmulc(a[r], wS0);
            twid_inv(a, wS1);
        }
#pragma unroll
        for (int r = 0; r < 8; r++) sE2[PAD(512 * r + 64 * lam + S)] = a[r];
        __syncthreads();

        // ---- step1': inverse DFT64 over k1, keep positions i<32 (r=0..3) ----
#pragma unroll
        for (int r = 0; r < 8; r++) a[r] = sE2[PAD(64 * S + 8 * r + lam)];
        inv64(a, lam, s_t64);
#pragma unroll
        for (int j = 0; j < 4; j++) {
            float2 v = make_float2(a[j].x * sc, a[j].y * sc);
            if (s == 0) c1r[j] = v;
            else if (s == 1) Pr[j] = cmul(c1r[j], v);
            else if (s == 2) c1r[j] = v;
            else {
                float2 p = cmul(c1r[j], v);
                Pr[j].x += p.x; Pr[j].y += p.y;
            }
        }
        // no extra sync: next round's step1 writes sE1; its readers finished
        // before the sync after the middle store above
    }

#pragma unroll
    for (int j = 0; j < 4; j++) {
        int m = 64 * lam + 512 * j + S;
        float2 psi = g_psi[m];
        out[(b * T + m) * 9 + c] = Pr[j].x * psi.x - Pr[j].y * psi.y;
    }
}

// ---------------- launch ----------------
extern "C" void kernel_launch(void* const* d_in, const int* in_sizes, int n_in,
                              void* d_out, int out_size) {
    const float* xd = (const float*)d_in[0];
    const float* A1 = (const float*)d_in[1];
    const float* A2 = (const float*)d_in[2];
    FnnW wf  = {(const float*)d_in[3],  (const float*)d_in[4],  (const float*)d_in[5],  (const float*)d_in[6]};
    FnnW wg  = {(const float*)d_in[7],  (const float*)d_in[8],  (const float*)d_in[9],  (const float*)d_in[10]};
    FnnW wfp = {(const float*)d_in[11], (const float*)d_in[12], (const float*)d_in[13], (const float*)d_in[14]};
    FnnW wgp = {(const float*)d_in[15], (const float*)d_in[16], (const float*)d_in[17], (const float*)d_in[18]};
    float* out = (float*)d_out;

    int smem_pre  = (512 + 4670 + 8 + 64) * sizeof(float2);    // ~42 KB (W role largest)
    int smem_main = SMEM_MAIN_F2 * sizeof(float2);             // 98,352 B
    cudaFuncSetAttribute(k_pre,  cudaFuncAttributeMaxDynamicSharedMemorySize, smem_pre);
    cudaFuncSetAttribute(k_main, cudaFuncAttributeMaxDynamicSharedMemorySize, smem_main);

    k_pre<<<197, 512, smem_pre>>>(xd, A1, A2, wf, wg, wfp, wgp);
    k_main<<<BATCH * 9, 512, smem_main>>>(out);
}

// round 9
// speedup vs baseline: 1.1276x; 1.1276x over previous
#include <cuda_runtime.h>
#include <math.h>

#define T    2048
#define NF   6142     // 3T-2
#define M0C  4094     // 2T-2
#define BATCH 64

// ---------------- device scratch ----------------
__device__ float2 g_tw[512];         // e^{-2pi i k/4096}, k<512
__device__ float2 g_psi[2048];
__device__ float2 g_W[4096];         // FFT(chirp) in (64S + 8lam + r) slot order
__device__ float2 g_UH[4 * 2048];    // Htilde * phaseU, PRE-PERMUTED to slot 512r + 8S + lam
__device__ float  g_A[9 * BATCH * T];
__device__ float  g_B[9 * BATCH * T];

__device__ __forceinline__ float2 cmul(float2 a, float2 b) {
    return make_float2(fmaf(a.x, b.x, -a.y * b.y), fmaf(a.x, b.y, a.y * b.x));
}
__device__ __forceinline__ float2 cmulc(float2 a, float2 b) {  // a * conj(b)
    return make_float2(fmaf(a.x, b.x, a.y * b.y), fmaf(a.y, b.x, -a.x * b.y));
}
__device__ __forceinline__ float2 cadd(float2 a, float2 b) { return make_float2(a.x + b.x, a.y + b.y); }
__device__ __forceinline__ float2 csub(float2 a, float2 b) { return make_float2(a.x - b.x, a.y - b.y); }
__device__ __forceinline__ int PAD(int e) { return e + (e >> 3) + (e >> 6); }

#define RC8 0.70710678118654752440f

__device__ __forceinline__ void fwd8(float2* a) {
    float2 F0=cadd(a[0],a[4]), F1=csub(a[0],a[4]);
    float2 G0=cadd(a[2],a[6]), G1=csub(a[2],a[6]);
    float2 H0=cadd(a[1],a[5]), H1=csub(a[1],a[5]);
    float2 K0=cadd(a[3],a[7]), K1=csub(a[3],a[7]);
    float2 E0=cadd(F0,G0), E2=csub(F0,G0);
    float2 E1=make_float2(F1.x+G1.y, F1.y-G1.x);
    float2 E3=make_float2(F1.x-G1.y, F1.y+G1.x);
    float2 O0=cadd(H0,K0), O2=csub(H0,K0);
    float2 O1=make_float2(H1.x+K1.y, H1.y-K1.x);
    float2 O3=make_float2(H1.x-K1.y, H1.y+K1.x);
    float2 t1=make_float2(RC8*(O1.x+O1.y),  RC8*(O1.y-O1.x));
    float2 t2=make_float2(O2.y, -O2.x);
    float2 t3=make_float2(RC8*(O3.y-O3.x), -RC8*(O3.x+O3.y));
    a[0]=cadd(E0,O0); a[4]=csub(E0,O0);
    a[1]=cadd(E1,t1); a[5]=csub(E1,t1);
    a[2]=cadd(E2,t2); a[6]=csub(E2,t2);
    a[3]=cadd(E3,t3); a[7]=csub(E3,t3);
}

__device__ __forceinline__ void inv8(float2* a) {
    float2 F0=cadd(a[0],a[4]), F1=csub(a[0],a[4]);
    float2 G0=cadd(a[2],a[6]), G1=csub(a[2],a[6]);
    float2 H0=cadd(a[1],a[5]), H1=csub(a[1],a[5]);
    float2 K0=cadd(a[3],a[7]), K1=csub(a[3],a[7]);
    float2 E0=cadd(F0,G0), E2=csub(F0,G0);
    float2 E1=make_float2(F1.x-G1.y, F1.y+G1.x);
    float2 E3=make_float2(F1.x+G1.y, F1.y-G1.x);
    float2 O0=cadd(H0,K0), O2=csub(H0,K0);
    float2 O1=make_float2(H1.x-K1.y, H1.y+K1.x);
    float2 O3=make_float2(H1.x+K1.y, H1.y-K1.x);
    float2 t1=make_float2(RC8*(O1.x-O1.y),  RC8*(O1.x+O1.y));
    float2 t2=make_float2(-O2.y, O2.x);
    float2 t3=make_float2(-RC8*(O3.x+O3.y), RC8*(O3.x-O3.y));
    a[0]=cadd(E0,O0); a[4]=csub(E0,O0);
    a[1]=cadd(E1,t1); a[5]=csub(E1,t1);
    a[2]=cadd(E2,t2); a[6]=csub(E2,t2);
    a[3]=cadd(E3,t3); a[7]=csub(E3,t3);
}

__device__ __forceinline__ void fwd8h(float2* a) {  // a[4..7] implied zero
    float2 a0=a[0], a1=a[1], a2=a[2], a3=a[3];
    float2 E0=cadd(a0,a2), E2=csub(a0,a2);
    float2 E1=make_float2(a0.x+a2.y, a0.y-a2.x);
    float2 E3=make_float2(a0.x-a2.y, a0.y+a2.x);
    float2 O0=cadd(a1,a3), O2=csub(a1,a3);
    float2 O1=make_float2(a1.x+a3.y, a1.y-a3.x);
    float2 O3=make_float2(a1.x-a3.y, a1.y+a3.x);
    float2 t1=make_float2(RC8*(O1.x+O1.y),  RC8*(O1.y-O1.x));
    float2 t2=make_float2(O2.y, -O2.x);
    float2 t3=make_float2(RC8*(O3.y-O3.x), -RC8*(O3.x+O3.y));
    a[0]=cadd(E0,O0); a[4]=csub(E0,O0);
    a[1]=cadd(E1,t1); a[5]=csub(E1,t1);
    a[2]=cadd(E2,t2); a[6]=csub(E2,t2);
    a[3]=cadd(E3,t3); a[7]=csub(E3,t3);
}

__device__ __forceinline__ void twid_fwd(float2* y, float2 w1) {
    float2 w2=cmul(w1,w1), w3=cmul(w2,w1), w4=cmul(w2,w2);
    float2 w5=cmul(w3,w2), w6=cmul(w3,w3), w7=cmul(w4,w3);
    y[1]=cmul(y[1],w1); y[2]=cmul(y[2],w2); y[3]=cmul(y[3],w3); y[4]=cmul(y[4],w4);
    y[5]=cmul(y[5],w5); y[6]=cmul(y[6],w6); y[7]=cmul(y[7],w7);
}
__device__ __forceinline__ void twid_inv(float2* y, float2 w1) {
    float2 w2=cmul(w1,w1), w3=cmul(w2,w1), w4=cmul(w2,w2);
    float2 w5=cmul(w3,w2), w6=cmul(w3,w3), w7=cmul(w4,w3);
    y[1]=cmulc(y[1],w1); y[2]=cmulc(y[2],w2); y[3]=cmulc(y[3],w3); y[4]=cmulc(y[4],w4);
    y[5]=cmulc(y[5],w5); y[6]=cmulc(y[6],w6); y[7]=cmulc(y[7],w7);
}

// 8x8 (lane-in-group x register) transpose via shfl_xor butterflies (lane bits 0..2).
__device__ __forceinline__ void transpose8(float2* a, int lane) {
#pragma unroll
    for (int b = 1; b < 8; b <<= 1) {
        bool hi = (lane & b) != 0;
#pragma unroll
        for (int jl = 0; jl < 8; jl++) {
            if (jl & b) continue;
            int jh = jl | b;
            float2 send = hi ? a[jl] : a[jh];
            float2 recv;
            recv.x = __shfl_xor_sync(0xffffffffu, send.x, b);
            recv.y = __shfl_xor_sync(0xffffffffu, send.y, b);
            if (hi) a[jl] = recv; else a[jh] = recv;
        }
    }
}

// warp-local 64-point DFT (8-lane groups): in a[r]=c[lam+8r], out (lam,r) <-> k=8r+lam
__device__ __forceinline__ void fwd64(float2* a, int lam, const float2* s_t64) {
    fwd8(a); twid_fwd(a, s_t64[lam]); transpose8(a, lam); fwd8(a);
}
__device__ __forceinline__ void inv64(float2* a, int lam, const float2* s_t64) {
    inv8(a); transpose8(a, lam); twid_inv(a, s_t64[lam]); inv8(a);
}

// ---------------- 3x3 helpers ----------------
__device__ __forceinline__ void rod(float vx, float vy, float vz, float* M) {
    float t2 = vx * vx + vy * vy + vz * vz;
    float th = sqrtf(t2);
    float a, bb;
    if (t2 < 1e-8f) { a = 1.0f - t2 * (1.0f / 6.0f); bb = 0.5f - t2 * (1.0f / 24.0f); }
    else { a = sinf(th) / th; float sh = sinf(0.5f * th); bb = 2.0f * sh * sh / t2; }
    float ct = 1.0f - bb * t2;
    M[0] = ct + bb * vx * vx; M[1] = bb * vx * vy - a * vz; M[2] = bb * vx * vz + a * vy;
    M[3] = bb * vy * vx + a * vz; M[4] = ct + bb * vy * vy; M[5] = bb * vy * vz - a * vx;
    M[6] = bb * vz * vx - a * vy; M[7] = bb * vz * vy + a * vx; M[8] = ct + bb * vz * vz;
}
__device__ __forceinline__ void mm3(const float* A, const float* B, float* C) {
    float t[9];
#pragma unroll
    for (int i = 0; i < 3; i++)
#pragma unroll
        for (int j = 0; j < 3; j++)
            t[3 * i + j] = A[3 * i] * B[j] + A[3 * i + 1] * B[3 + j] + A[3 * i + 2] * B[6 + j];
#pragma unroll
    for (int k = 0; k < 9; k++) C[k] = t[k];
}
__device__ __forceinline__ void inv3(const float* A, float* B) {
    float c00 = A[4] * A[8] - A[5] * A[7];
    float c01 = A[5] * A[6] - A[3] * A[8];
    float c02 = A[3] * A[7] - A[4] * A[6];
    float id = 1.0f / (A[0] * c00 + A[1] * c01 + A[2] * c02);
    B[0] = c00 * id; B[1] = (A[2] * A[7] - A[1] * A[8]) * id; B[2] = (A[1] * A[5] - A[2] * A[4]) * id;
    B[3] = c01 * id; B[4] = (A[0] * A[8] - A[2] * A[6]) * id; B[5] = (A[2] * A[3] - A[0] * A[5]) * id;
    B[6] = c02 * id; B[7] = (A[1] * A[6] - A[0] * A[7]) * id; B[8] = (A[0] * A[4] - A[1] * A[3]) * id;
}

struct FnnW { const float *w1, *b1, *w2, *b2; };

extern __shared__ float2 smem_c[];

// ================= fused precompute kernel =================
__global__ __launch_bounds__(512) void k_pre(
    const float* __restrict__ xd, const float* __restrict__ A1, const float* __restrict__ A2,
    FnnW wf, FnnW wg, FnnW wfp, FnnW wgp)
{
    int blk = blockIdx.x, tid = threadIdx.x;

    if (blk < 64) {
        float* sP = (float*)smem_c;        // 256*9
        float* sv = sP + 2304;             // 6
        int b = blk;
        if (tid == 0) {
            sv[0] = A1[7] - A1[5]; sv[1] = A1[2] - A1[6]; sv[2] = A1[3] - A1[1];
            sv[3] = A2[7] - A2[5]; sv[4] = A2[2] - A2[6]; sv[5] = A2[3] - A2[1];
        }
        __syncthreads();
        float v1x = sv[0], v1y = sv[1], v1z = sv[2], v2x = sv[3], v2y = sv[4], v2z = sv[5];
        bool act = tid < 256;
        float mine[9];
        int t0 = tid * 8;
        if (act) {
            float P[9] = {1, 0, 0, 0, 1, 0, 0, 0, 1};
            for (int tt = 0; tt < 8; tt++) {
                int t = t0 + tt;
                if (t == 0) continue;
                float z1 = xd[(b * T + t) * 2], z2 = xd[(b * T + t) * 2 + 1];
                float M[9];
                rod(z1 * v1x + z2 * v2x, z1 * v1y + z2 * v2y, z1 * v1z + z2 * v2z, M);
                mm3(P, M, P);
            }
#pragma unroll
            for (int k = 0; k < 9; k++) { mine[k] = P[k]; sP[tid * 9 + k] = P[k]; }
        }
        __syncthreads();
        for (int off = 1; off < 256; off <<= 1) {
            float Lm[9];
            bool a2 = act && tid >= off;
            if (a2)
#pragma unroll
                for (int k = 0; k < 9; k++) Lm[k] = sP[(tid - off) * 9 + k];
            __syncthreads();
            if (a2) {
                mm3(Lm, mine, mine);
#pragma unroll
                for (int k = 0; k < 9; k++) sP[tid * 9 + k] = mine[k];
            }
            __syncthreads();
        }
        if (act) {
            float X[9] = {1, 0, 0, 0, 1, 0, 0, 0, 1};
            if (tid > 0)
#pragma unroll
                for (int k = 0; k < 9; k++) X[k] = sP[(tid - 1) * 9 + k];
            for (int tt = 0; tt < 8; tt++) {
                int t = t0 + tt;
                if (t != 0) {
                    float z1 = xd[(b * T + t) * 2], z2 = xd[(b * T + t) * 2 + 1];
                    float M[9];
                    rod(z1 * v1x + z2 * v2x, z1 * v1y + z2 * v2y, z1 * v1z + z2 * v2z, M);
                    mm3(X, M, X);
                }
                float Bi[9];
                inv3(X, Bi);
#pragma unroll
                for (int c = 0; c < 9; c++) {
                    g_A[(c * BATCH + b) * T + t] = X[c];
                    g_B[(c * BATCH + b) * T + t] = Bi[c];
                }
            }
        }
    } else if (blk < 68) {
        int i = (blk - 64) * 512 + tid;
        float s, c;
        if (i < 512) {
            sincospif((float)i / 2048.0f, &s, &c);
            g_tw[i] = make_float2(c, -s);
        }
        long long j = i;
        long long e2 = (2LL * (T - 1) * (M0C + j) + j * j) % NF;
        sincospif(2.0f * (float)e2 / (float)NF, &s, &c);
        g_psi[i] = make_float2(c, s);
    } else if (blk == 68) {
        // ---------------- W role: same 64x64 pipeline as k_main forward ----------------
        float2* s_tw  = smem_c;              // 512
        float2* s_buf = smem_c + 512;        // 4670
        float2* s_t64 = smem_c + 512 + 4670; // 8
        int t = tid;
        {
            float s, c;
            sincospif((float)t / 2048.0f, &s, &c);
            s_tw[t] = make_float2(c, -s);
        }
        __syncthreads();
        if (t < 8) s_t64[t] = s_tw[64 * t];
        __syncthreads();
        int lam = t & 7, S = t >> 3;
        float2 a[8];
#pragma unroll
        for (int r = 0; r < 8; r++) {
            int n = 64 * (lam + 8 * r) + S;
            float2 v;
            if (n == 2048) v = make_float2(0.f, 0.f);
            else {
                long long k = (n < 2048) ? n : (4096 - n);
                long long idx = (k * k) % (2LL * NF);
                float s, c;
                sincospif((float)idx / (float)NF, &s, &c);
                v = make_float2(c, -s);
            }
            a[r] = v;
        }
        fwd64(a, lam, s_t64);
        {
            float2 w0 = s_tw[S * lam];
#pragma unroll
            for (int r = 0; r < 8; r++) a[r] = cmul(a[r], w0);
            twid_fwd(a, s_tw[8 * S]);
        }
#pragma unroll
        for (int r = 0; r < 8; r++) s_buf[PAD(512 * r + 64 * lam + S)] = a[r];
        __syncthreads();
#pragma unroll
        for (int r = 0; r < 8; r++) a[r] = s_buf[PAD(64 * S + 8 * r + lam)];
        fwd64(a, lam, s_t64);
#pragma unroll
        for (int r = 0; r < 8; r++) g_W[64 * S + 8 * lam + r] = a[r];
    } else {
        // ---------------- H role: 128 blocks, 64 j per block, 4 j per warp ----------------
        // g_UH written PRE-PERMUTED: slot(e) = 512*(e>>9) + 8*(e&63) + ((e>>6)&7)
        float* s_q = (float*)smem_c;   // 2048 floats
        int hb = blk - 69;             // 0..127
        int q = hb >> 5;               // 32 blocks per filter
        int jbase = (hb & 31) << 6;    // 64 j's per block
        FnnW W = (q == 0) ? wf : (q == 1) ? wg : (q == 2) ? wfp : wgp;
        for (int p = tid; p < 2048; p += 512) {
            float x = (q == 0 || q == 2) ? (float)(T - 1 - p) : (float)p;
            float z = W.b2[0];
#pragma unroll
            for (int h = 0; h < 5; h++)
                z += W.w2[h] * tanhf(W.w1[h] * x + W.b1[h]);
            s_q[p] = z * expf(-5.0f * x);
        }
        __syncthreads();
        int warp = tid >> 5, lane = tid & 31;
        float2 ph[4], st[4], acc[4];
#pragma unroll
        for (int u = 0; u < 4; u++) {
            int j = jbase + 4 * warp + u;
            long long base = j + (T - 1);
            long long idx0 = (base * (long long)(lane + T - 1)) % NF;
            float s, c;
            sincospif(2.0f * (float)idx0 / (float)NF, &s, &c);
            ph[u] = make_float2(c, -s);
            long long idxs = (base * 32LL) % NF;
            sincospif(2.0f * (float)idxs / (float)NF, &s, &c);
            st[u] = make_float2(c, -s);
            acc[u] = make_float2(0.f, 0.f);
        }
#pragma unroll 4
        for (int it = 0; it < 64; it++) {
            float v = s_q[lane + 32 * it];
#pragma unroll
            for (int u = 0; u < 4; u++) {
                acc[u].x = fmaf(v, ph[u].x, acc[u].x);
                acc[u].y = fmaf(v, ph[u].y, acc[u].y);
                ph[u] = cmul(ph[u], st[u]);
            }
        }
#pragma unroll
        for (int u = 0; u < 4; u++) {
            for (int off = 16; off; off >>= 1) {
                acc[u].x += __shfl_down_sync(0xffffffffu, acc[u].x, off);
                acc[u].y += __shfl_down_sync(0xffffffffu, acc[u].y, off);
            }
        }
        if (lane == 0) {
#pragma unroll
            for (int u = 0; u < 4; u++) {
                int j = jbase + 4 * warp + u;
                long long idxU = (2LL * j * M0C + (long long)j * j) % (2LL * NF);
                float s, c;
                sincospif((float)idxU / (float)NF, &s, &c);
                int slot = 512 * (j >> 9) + 8 * (j & 63) + ((j >> 6) & 7);
                g_UH[q * 2048 + slot] = cmul(acc[u], make_float2(c, s));
            }
        }
    }
}

// ================= main kernel: 64x64 CT, coalesced boundaries =================
// smem: tw 512 | Z 2334 | E1 4670 | E2 4670 | t512 64 | t64 8 | t256 32 | t32 4 = 12294 f2
#define SMEM_MAIN_F2 (512 + 2334 + 4670 + 4670 + 64 + 8 + 32 + 4)

__global__ __launch_bounds__(512, 2) void k_main(float* __restrict__ out) {
    float2* s_tw   = smem_c;            // 512
    float2* s_Z    = smem_c + 512;      // 2334 (padded 2048)
    float2* sE1    = smem_c + 2846;     // 4670
    float2* sE2    = sE1 + 4670;        // 4670
    float2* s_t512 = sE2 + 4670;        // 64
    float2* s_t64  = s_t512 + 64;       // 8
    float2* s_t256 = s_t64 + 8;         // 32
    float2* s_t32  = s_t256 + 32;       // 4

    int b = blockIdx.x / 9, c = blockIdx.x % 9;
    int t = threadIdx.x;

    s_tw[t] = g_tw[t & 511];
    if (t < 64) s_t512[t] = g_tw[8 * t];
    if (t < 8)  s_t64[t]  = g_tw[64 * t];
    if (t < 32) s_t256[t] = g_tw[16 * t];
    if (t < 4)  s_t32[t]  = g_tw[128 * t];
    __syncthreads();

    const float* Ar = g_A + (c * BATCH + b) * T;
    const float* Ai = g_B + (c * BATCH + b) * T;

    // ===== phase 0: packed 2048-point FFT (256 active threads, ping-pong E1/E2) =====
    float2 a[8];
    if (t < 256) {
#pragma unroll
        for (int j = 0; j < 8; j++) {
            int i = t + 256 * j;
            a[j] = make_float2(Ai[i], Ar[i]);   // z = Xir + i*Xr
        }
        fwd8(a); twid_fwd(a, s_tw[2 * t]);
#pragma unroll
        for (int r = 0; r < 8; r++) sE1[PAD(256 * r + t)] = a[r];
    }
    __syncthreads();
    if (t < 256) {  // stage2: S=256 q=32  E1->E2
        int pb = 256 * (t >> 5), pk = t & 31;
#pragma unroll
        for (int j = 0; j < 8; j++) a[j] = sE1[PAD(pb + pk + 32 * j)];
        fwd8(a); twid_fwd(a, s_t256[pk]);
#pragma unroll
        for (int r = 0; r < 8; r++) sE2[PAD(pb + 32 * r + pk)] = a[r];
    }
    __syncthreads();
    if (t < 256) {  // stage3: S=32 q=4  E2->E1
        int pb = 32 * (t >> 2), pk = t & 3;
#pragma unroll
        for (int j = 0; j < 8; j++) a[j] = sE2[PAD(pb + pk + 4 * j)];
        fwd8(a); twid_fwd(a, s_t32[pk]);
#pragma unroll
        for (int r = 0; r < 8; r++) sE1[PAD(pb + 4 * r + pk)] = a[r];
    }
    __syncthreads();
    if (t < 256) {  // stage4: radix-4 x2, unscramble  E1->s_Z (padded)
#pragma unroll
        for (int h = 0; h < 2; h++) {
            int B = 2 * t + h;
            float2 b4[4];
#pragma unroll
            for (int j = 0; j < 4; j++) b4[j] = sE1[PAD(4 * B + j)];
            float2 e0 = cadd(b4[0], b4[2]), e1 = csub(b4[0], b4[2]);
            float2 o0 = cadd(b4[1], b4[3]), o1 = csub(b4[1], b4[3]);
            float2 y0 = cadd(e0, o0), y2 = csub(e0, o0);
            float2 y1 = make_float2(e1.x + o1.y, e1.y - o1.x);
            float2 y3 = make_float2(e1.x - o1.y, e1.y + o1.x);
            int f = (B >> 6) + 8 * ((B >> 3) & 7) + 64 * (B & 7);
            s_Z[PAD(f)] = y0; s_Z[PAD(f + 512)] = y1;
            s_Z[PAD(f + 1024)] = y2; s_Z[PAD(f + 1536)] = y3;
        }
    }
    __syncthreads();

    // ===== chirp rounds (64x64 Cooley-Tukey) =====
    float2 c1r[4], Pr[4];
    const float sc = 1.0f / (4096.0f * (float)NF);
    const int lam = t & 7;     // lane within 8-group
    const int S   = t >> 3;    // sequence index (step1: j) / k1 (middle)
    const float2 w64l = s_t64[lam];
    const float2 wS0  = s_tw[S * lam];   // w4096^{S*lam}
    const float2 wS1  = s_tw[8 * S];     // w4096^{8S}

#pragma unroll
    for (int s = 0; s < 4; s++) {
        bool useIr = (s == 0 || s == 2);
        const float2* UH = g_UH + s * 2048;

        // ---- step1: gen u (half-zero), warp-local DFT64 over i, outer twiddle ----
#pragma unroll
        for (int r = 0; r < 4; r++) {
            int e = 64 * lam + 512 * r + S;          // e < 2048
            float2 Zj = s_Z[PAD(e)];
            float2 Zm = s_Z[PAD((2048 - e) & 2047)];
            float2 X = useIr
                ? make_float2(0.5f * (Zj.x + Zm.x), 0.5f * (Zj.y - Zm.y))
                : make_float2(0.5f * (Zj.y + Zm.y), 0.5f * (Zm.x - Zj.x));
            a[r] = cmul(X, UH[512 * r + t]);         // coalesced (pre-permuted)
        }
        fwd8h(a); twid_fwd(a, w64l); transpose8(a, lam); fwd8(a);
        {
#pragma unroll
            for (int r = 0; r < 8; r++) a[r] = cmul(a[r], wS0);
            twid_fwd(a, wS1);
        }
#pragma unroll
        for (int r = 0; r < 8; r++) sE1[PAD(512 * r + 64 * lam + S)] = a[r];
        __syncthreads();

        // ---- middle: DFT64 over j + W + invDFT64 + conj outer twiddle (registers) ----
#pragma unroll
        for (int r = 0; r < 8; r++) a[r] = sE1[PAD(64 * S + 8 * r + lam)];
        fwd64(a, lam, s_t64);
        {
            const float4* W4 = (const float4*)(g_W + 64 * S + 8 * lam);
            float4 w = W4[0];
            a[0] = cmul(a[0], make_float2(w.x, w.y)); a[1] = cmul(a[1], make_float2(w.z, w.w));
            w = W4[1];
            a[2] = cmul(a[2], make_float2(w.x, w.y)); a[3] = cmul(a[3], make_float2(w.z, w.w));
            w = W4[2];
            a[4] = cmul(a[4], make_float2(w.x, w.y)); a[5] = cmul(a[5], make_float2(w.z, w.w));
            w = W4[3];
            a[6] = cmul(a[6], make_float2(w.x, w.y)); a[7] = cmul(a[7], make_float2(w.z, w.w));
        }
        inv64(a, lam, s_t64);
        {
#pragma unroll
            for (int r = 0; r < 8; r++) a[r] = cmulc(a[r], wS0);
            twid_inv(a, wS1);
        }
#pragma unroll
        for (int r = 0; r < 8; r++) sE2[PAD(512 * r + 64 * lam + S)] = a[r];
        __syncthreads();

        // ---- step1': inverse DFT64 over k1, keep positions i<32 (r=0..3) ----
#pragma unroll
        for (int r = 0; r < 8; r++) a[r] = sE2[PAD(64 * S + 8 * r + lam)];
        inv64(a, lam, s_t64);
#pragma unroll
        for (int j = 0; j < 4; j++) {
            float2 v = make_float2(a[j].x * sc, a[j].y * sc);
            if (s == 0) c1r[j] = v;
            else if (s == 1) Pr[j] = cmul(c1r[j], v);
            else if (s == 2) c1r[j] = v;
            else {
                float2 p = cmul(c1r[j], v);
                Pr[j].x += p.x; Pr[j].y += p.y;
            }
        }
        // no extra sync: next round's step1 writes sE1; its readers finished
        // before the sync after the middle store above
    }

    // ===== permute results to m = t + 512j layout (coalesced psi/out) =====
    __syncthreads();   // ensure all step1' reads of sE2 done; sE1 free since mid-sync
#pragma unroll
    for (int j = 0; j < 4; j++) sE1[PAD(512 * j + 64 * lam + S)] = Pr[j];
    __syncthreads();
#pragma unroll
    for (int j = 0; j < 4; j++) {
        float2 p = sE1[PAD(512 * j + t)];
        int m = t + 512 * j;
        float2 psi = g_psi[m];
        out[(b * T + m) * 9 + c] = p.x * psi.x - p.y * psi.y;
    }
}

// ---------------- launch ----------------
extern "C" void kernel_launch(void* const* d_in, const int* in_sizes, int n_in,
                              void* d_out, int out_size) {
    const float* xd = (const float*)d_in[0];
    const float* A1 = (const float*)d_in[1];
    const float* A2 = (const float*)d_in[2];
    FnnW wf  = {(const float*)d_in[3],  (const float*)d_in[4],  (const float*)d_in[5],  (const float*)d_in[6]};
    FnnW wg  = {(const float*)d_in[7],  (const float*)d_in[8],  (const float*)d_in[9],  (const float*)d_in[10]};
    FnnW wfp = {(const float*)d_in[11], (const float*)d_in[12], (const float*)d_in[13], (const float*)d_in[14]};
    FnnW wgp = {(const float*)d_in[15], (const float*)d_in[16], (const float*)d_in[17], (const float*)d_in[18]};
    float* out = (float*)d_out;

    int smem_pre  = (512 + 4670 + 8 + 64) * sizeof(float2);    // ~42 KB (W role largest)
    int smem_main = SMEM_MAIN_F2 * sizeof(float2);             // 98,352 B
    cudaFuncSetAttribute(k_pre,  cudaFuncAttributeMaxDynamicSharedMemorySize, smem_pre);
    cudaFuncSetAttribute(k_main, cudaFuncAttributeMaxDynamicSharedMemorySize, smem_main);

    k_pre<<<197, 512, smem_pre>>>(xd, A1, A2, wf, wg, wfp, wgp);
    k_main<<<BATCH * 9, 512, smem_main>>>(out);
}

// round 10
// speedup vs baseline: 1.3223x; 1.1726x over previous
#include <cuda_runtime.h>
#include <math.h>

#define T    2048
#define NF   6142     // 3T-2
#define M0C  4094     // 2T-2
#define BATCH 64

// ---------------- device scratch ----------------
__device__ float2 g_tw[512];         // e^{-2pi i k/4096}, k<512
__device__ float2 g_psi[2048];
__device__ float2 g_W[4096];         // FFT(chirp) in (64S + 8lam + r) slot order
__device__ float2 g_UH[4 * 2048];    // Htilde * phaseU, PRE-PERMUTED to slot 512r + 8S + lam
__device__ float  g_A[9 * BATCH * T];
__device__ float  g_B[9 * BATCH * T];

__device__ __forceinline__ float2 cmul(float2 a, float2 b) {
    return make_float2(fmaf(a.x, b.x, -a.y * b.y), fmaf(a.x, b.y, a.y * b.x));
}
__device__ __forceinline__ float2 cmulc(float2 a, float2 b) {  // a * conj(b)
    return make_float2(fmaf(a.x, b.x, a.y * b.y), fmaf(a.y, b.x, -a.x * b.y));
}
__device__ __forceinline__ float2 cadd(float2 a, float2 b) { return make_float2(a.x + b.x, a.y + b.y); }
__device__ __forceinline__ float2 csub(float2 a, float2 b) { return make_float2(a.x - b.x, a.y - b.y); }
__device__ __forceinline__ int PAD(int e) { return e + (e >> 3) + (e >> 6); }

#define RC8 0.70710678118654752440f

__device__ __forceinline__ void fwd8(float2* a) {
    float2 F0=cadd(a[0],a[4]), F1=csub(a[0],a[4]);
    float2 G0=cadd(a[2],a[6]), G1=csub(a[2],a[6]);
    float2 H0=cadd(a[1],a[5]), H1=csub(a[1],a[5]);
    float2 K0=cadd(a[3],a[7]), K1=csub(a[3],a[7]);
    float2 E0=cadd(F0,G0), E2=csub(F0,G0);
    float2 E1=make_float2(F1.x+G1.y, F1.y-G1.x);
    float2 E3=make_float2(F1.x-G1.y, F1.y+G1.x);
    float2 O0=cadd(H0,K0), O2=csub(H0,K0);
    float2 O1=make_float2(H1.x+K1.y, H1.y-K1.x);
    float2 O3=make_float2(H1.x-K1.y, H1.y+K1.x);
    float2 t1=make_float2(RC8*(O1.x+O1.y),  RC8*(O1.y-O1.x));
    float2 t2=make_float2(O2.y, -O2.x);
    float2 t3=make_float2(RC8*(O3.y-O3.x), -RC8*(O3.x+O3.y));
    a[0]=cadd(E0,O0); a[4]=csub(E0,O0);
    a[1]=cadd(E1,t1); a[5]=csub(E1,t1);
    a[2]=cadd(E2,t2); a[6]=csub(E2,t2);
    a[3]=cadd(E3,t3); a[7]=csub(E3,t3);
}

__device__ __forceinline__ void inv8(float2* a) {
    float2 F0=cadd(a[0],a[4]), F1=csub(a[0],a[4]);
    float2 G0=cadd(a[2],a[6]), G1=csub(a[2],a[6]);
    float2 H0=cadd(a[1],a[5]), H1=csub(a[1],a[5]);
    float2 K0=cadd(a[3],a[7]), K1=csub(a[3],a[7]);
    float2 E0=cadd(F0,G0), E2=csub(F0,G0);
    float2 E1=make_float2(F1.x-G1.y, F1.y+G1.x);
    float2 E3=make_float2(F1.x+G1.y, F1.y-G1.x);
    float2 O0=cadd(H0,K0), O2=csub(H0,K0);
    float2 O1=make_float2(H1.x-K1.y, H1.y+K1.x);
    float2 O3=make_float2(H1.x+K1.y, H1.y-K1.x);
    float2 t1=make_float2(RC8*(O1.x-O1.y),  RC8*(O1.x+O1.y));
    float2 t2=make_float2(-O2.y, O2.x);
    float2 t3=make_float2(-RC8*(O3.x+O3.y), RC8*(O3.x-O3.y));
    a[0]=cadd(E0,O0); a[4]=csub(E0,O0);
    a[1]=cadd(E1,t1); a[5]=csub(E1,t1);
    a[2]=cadd(E2,t2); a[6]=csub(E2,t2);
    a[3]=cadd(E3,t3); a[7]=csub(E3,t3);
}

__device__ __forceinline__ void fwd8h(float2* a) {  // a[4..7] implied zero
    float2 a0=a[0], a1=a[1], a2=a[2], a3=a[3];
    float2 E0=cadd(a0,a2), E2=csub(a0,a2);
    float2 E1=make_float2(a0.x+a2.y, a0.y-a2.x);
    float2 E3=make_float2(a0.x-a2.y, a0.y+a2.x);
    float2 O0=cadd(a1,a3), O2=csub(a1,a3);
    float2 O1=make_float2(a1.x+a3.y, a1.y-a3.x);
    float2 O3=make_float2(a1.x-a3.y, a1.y+a3.x);
    float2 t1=make_float2(RC8*(O1.x+O1.y),  RC8*(O1.y-O1.x));
    float2 t2=make_float2(O2.y, -O2.x);
    float2 t3=make_float2(RC8*(O3.y-O3.x), -RC8*(O3.x+O3.y));
    a[0]=cadd(E0,O0); a[4]=csub(E0,O0);
    a[1]=cadd(E1,t1); a[5]=csub(E1,t1);
    a[2]=cadd(E2,t2); a[6]=csub(E2,t2);
    a[3]=cadd(E3,t3); a[7]=csub(E3,t3);
}

__device__ __forceinline__ void twid_fwd(float2* y, float2 w1) {
    float2 w2=cmul(w1,w1), w3=cmul(w2,w1), w4=cmul(w2,w2);
    float2 w5=cmul(w3,w2), w6=cmul(w3,w3), w7=cmul(w4,w3);
    y[1]=cmul(y[1],w1); y[2]=cmul(y[2],w2); y[3]=cmul(y[3],w3); y[4]=cmul(y[4],w4);
    y[5]=cmul(y[5],w5); y[6]=cmul(y[6],w6); y[7]=cmul(y[7],w7);
}
__device__ __forceinline__ void twid_inv(float2* y, float2 w1) {
    float2 w2=cmul(w1,w1), w3=cmul(w2,w1), w4=cmul(w2,w2);
    float2 w5=cmul(w3,w2), w6=cmul(w3,w3), w7=cmul(w4,w3);
    y[1]=cmulc(y[1],w1); y[2]=cmulc(y[2],w2); y[3]=cmulc(y[3],w3); y[4]=cmulc(y[4],w4);
    y[5]=cmulc(y[5],w5); y[6]=cmulc(y[6],w6); y[7]=cmulc(y[7],w7);
}

// 8x8 (lane-in-group x register) transpose via shfl_xor butterflies (lane bits 0..2).
__device__ __forceinline__ void transpose8(float2* a, int lane) {
#pragma unroll
    for (int b = 1; b < 8; b <<= 1) {
        bool hi = (lane & b) != 0;
#pragma unroll
        for (int jl = 0; jl < 8; jl++) {
            if (jl & b) continue;
            int jh = jl | b;
            float2 send = hi ? a[jl] : a[jh];
            float2 recv;
            recv.x = __shfl_xor_sync(0xffffffffu, send.x, b);
            recv.y = __shfl_xor_sync(0xffffffffu, send.y, b);
            if (hi) a[jl] = recv; else a[jh] = recv;
        }
    }
}

// warp-local 64-point DFT (8-lane groups): in a[r]=c[lam+8r], out (lam,r) <-> k=8r+lam
__device__ __forceinline__ void fwd64(float2* a, int lam, const float2* s_t64) {
    fwd8(a); twid_fwd(a, s_t64[lam]); transpose8(a, lam); fwd8(a);
}
__device__ __forceinline__ void inv64(float2* a, int lam, const float2* s_t64) {
    inv8(a); transpose8(a, lam); twid_inv(a, s_t64[lam]); inv8(a);
}

// ---------------- 3x3 helpers ----------------
__device__ __forceinline__ void rod(float vx, float vy, float vz, float* M) {
    float t2 = vx * vx + vy * vy + vz * vz;
    float th = sqrtf(t2);
    float a, bb;
    if (t2 < 1e-8f) { a = 1.0f - t2 * (1.0f / 6.0f); bb = 0.5f - t2 * (1.0f / 24.0f); }
    else { a = sinf(th) / th; float sh = sinf(0.5f * th); bb = 2.0f * sh * sh / t2; }
    float ct = 1.0f - bb * t2;
    M[0] = ct + bb * vx * vx; M[1] = bb * vx * vy - a * vz; M[2] = bb * vx * vz + a * vy;
    M[3] = bb * vy * vx + a * vz; M[4] = ct + bb * vy * vy; M[5] = bb * vy * vz - a * vx;
    M[6] = bb * vz * vx - a * vy; M[7] = bb * vz * vy + a * vx; M[8] = ct + bb * vz * vz;
}
__device__ __forceinline__ void mm3(const float* A, const float* B, float* C) {
    float t[9];
#pragma unroll
    for (int i = 0; i < 3; i++)
#pragma unroll
        for (int j = 0; j < 3; j++)
            t[3 * i + j] = A[3 * i] * B[j] + A[3 * i + 1] * B[3 + j] + A[3 * i + 2] * B[6 + j];
#pragma unroll
    for (int k = 0; k < 9; k++) C[k] = t[k];
}
__device__ __forceinline__ void inv3(const float* A, float* B) {
    float c00 = A[4] * A[8] - A[5] * A[7];
    float c01 = A[5] * A[6] - A[3] * A[8];
    float c02 = A[3] * A[7] - A[4] * A[6];
    float id = 1.0f / (A[0] * c00 + A[1] * c01 + A[2] * c02);
    B[0] = c00 * id; B[1] = (A[2] * A[7] - A[1] * A[8]) * id; B[2] = (A[1] * A[5] - A[2] * A[4]) * id;
    B[3] = c01 * id; B[4] = (A[0] * A[8] - A[2] * A[6]) * id; B[5] = (A[2] * A[3] - A[0] * A[5]) * id;
    B[6] = c02 * id; B[7] = (A[1] * A[6] - A[0] * A[7]) * id; B[8] = (A[0] * A[4] - A[1] * A[3]) * id;
}

struct FnnW { const float *w1, *b1, *w2, *b2; };

extern __shared__ float2 smem_c[];

// ================= fused precompute kernel =================
__global__ __launch_bounds__(512) void k_pre(
    const float* __restrict__ xd, const float* __restrict__ A1, const float* __restrict__ A2,
    FnnW wf, FnnW wg, FnnW wfp, FnnW wgp)
{
    int blk = blockIdx.x, tid = threadIdx.x;

    if (blk < 64) {
        // ---------------- scan role: 512 threads x 4-element chains ----------------
        float* sP = (float*)smem_c;        // 512*9
        float* sv = sP + 4608;             // 6
        int b = blk;
        if (tid == 0) {
            sv[0] = A1[7] - A1[5]; sv[1] = A1[2] - A1[6]; sv[2] = A1[3] - A1[1];
            sv[3] = A2[7] - A2[5]; sv[4] = A2[2] - A2[6]; sv[5] = A2[3] - A2[1];
        }
        __syncthreads();
        float v1x = sv[0], v1y = sv[1], v1z = sv[2], v2x = sv[3], v2y = sv[4], v2z = sv[5];
        float mine[9];
        int t0 = tid * 4;
        {
            float P[9] = {1, 0, 0, 0, 1, 0, 0, 0, 1};
            for (int tt = 0; tt < 4; tt++) {
                int t = t0 + tt;
                if (t == 0) continue;
                float z1 = xd[(b * T + t) * 2], z2 = xd[(b * T + t) * 2 + 1];
                float M[9];
                rod(z1 * v1x + z2 * v2x, z1 * v1y + z2 * v2y, z1 * v1z + z2 * v2z, M);
                mm3(P, M, P);
            }
#pragma unroll
            for (int k = 0; k < 9; k++) { mine[k] = P[k]; sP[tid * 9 + k] = P[k]; }
        }
        __syncthreads();
        for (int off = 1; off < 512; off <<= 1) {
            float Lm[9];
            bool a2 = tid >= off;
            if (a2)
#pragma unroll
                for (int k = 0; k < 9; k++) Lm[k] = sP[(tid - off) * 9 + k];
            __syncthreads();
            if (a2) {
                mm3(Lm, mine, mine);
#pragma unroll
                for (int k = 0; k < 9; k++) sP[tid * 9 + k] = mine[k];
            }
            __syncthreads();
        }
        {
            float X[9] = {1, 0, 0, 0, 1, 0, 0, 0, 1};
            if (tid > 0)
#pragma unroll
                for (int k = 0; k < 9; k++) X[k] = sP[(tid - 1) * 9 + k];
            for (int tt = 0; tt < 4; tt++) {
                int t = t0 + tt;
                if (t != 0) {
                    float z1 = xd[(b * T + t) * 2], z2 = xd[(b * T + t) * 2 + 1];
                    float M[9];
                    rod(z1 * v1x + z2 * v2x, z1 * v1y + z2 * v2y, z1 * v1z + z2 * v2z, M);
                    mm3(X, M, X);
                }
                float Bi[9];
                inv3(X, Bi);
#pragma unroll
                for (int c = 0; c < 9; c++) {
                    g_A[(c * BATCH + b) * T + t] = X[c];
                    g_B[(c * BATCH + b) * T + t] = Bi[c];
                }
            }
        }
    } else if (blk < 68) {
        int i = (blk - 64) * 512 + tid;
        float s, c;
        if (i < 512) {
            sincospif((float)i / 2048.0f, &s, &c);
            g_tw[i] = make_float2(c, -s);
        }
        long long j = i;
        long long e2 = (2LL * (T - 1) * (M0C + j) + j * j) % NF;
        sincospif(2.0f * (float)e2 / (float)NF, &s, &c);
        g_psi[i] = make_float2(c, s);
    } else if (blk == 68) {
        // ---------------- W role: same 64x64 pipeline as k_main forward ----------------
        float2* s_tw  = smem_c;              // 512
        float2* s_buf = smem_c + 512;        // 4670
        float2* s_t64 = smem_c + 512 + 4670; // 8
        int t = tid;
        {
            float s, c;
            sincospif((float)t / 2048.0f, &s, &c);
            s_tw[t] = make_float2(c, -s);
        }
        __syncthreads();
        if (t < 8) s_t64[t] = s_tw[64 * t];
        __syncthreads();
        int lam = t & 7, S = t >> 3;
        float2 a[8];
#pragma unroll
        for (int r = 0; r < 8; r++) {
            int n = 64 * (lam + 8 * r) + S;
            float2 v;
            if (n == 2048) v = make_float2(0.f, 0.f);
            else {
                long long k = (n < 2048) ? n : (4096 - n);
                long long idx = (k * k) % (2LL * NF);
                float s, c;
                sincospif((float)idx / (float)NF, &s, &c);
                v = make_float2(c, -s);
            }
            a[r] = v;
        }
        fwd64(a, lam, s_t64);
        {
            float2 w0 = s_tw[S * lam];
#pragma unroll
            for (int r = 0; r < 8; r++) a[r] = cmul(a[r], w0);
            twid_fwd(a, s_tw[8 * S]);
        }
#pragma unroll
        for (int r = 0; r < 8; r++) s_buf[PAD(512 * r + 64 * lam + S)] = a[r];
        __syncthreads();
#pragma unroll
        for (int r = 0; r < 8; r++) a[r] = s_buf[PAD(64 * S + 8 * r + lam)];
        fwd64(a, lam, s_t64);
#pragma unroll
        for (int r = 0; r < 8; r++) g_W[64 * S + 8 * lam + r] = a[r];
    } else {
        // ---------------- H role: 128 blocks, 64 j per block, 4 j per warp ----------------
        // g_UH written PRE-PERMUTED: slot(e) = 512*(e>>9) + 8*(e&63) + ((e>>6)&7)
        float* s_q = (float*)smem_c;   // 2048 floats
        int hb = blk - 69;             // 0..127
        int q = hb >> 5;               // 32 blocks per filter
        int jbase = (hb & 31) << 6;    // 64 j's per block
        FnnW W = (q == 0) ? wf : (q == 1) ? wg : (q == 2) ? wfp : wgp;
        for (int p = tid; p < 2048; p += 512) {
            float x = (q == 0 || q == 2) ? (float)(T - 1 - p) : (float)p;
            float z = W.b2[0];
#pragma unroll
            for (int h = 0; h < 5; h++)
                z += W.w2[h] * tanhf(W.w1[h] * x + W.b1[h]);
            s_q[p] = z * expf(-5.0f * x);
        }
        __syncthreads();
        int warp = tid >> 5, lane = tid & 31;
        float2 ph[4], st[4], acc[4];
#pragma unroll
        for (int u = 0; u < 4; u++) {
            int j = jbase + 4 * warp + u;
            long long base = j + (T - 1);
            long long idx0 = (base * (long long)(lane + T - 1)) % NF;
            float s, c;
            sincospif(2.0f * (float)idx0 / (float)NF, &s, &c);
            ph[u] = make_float2(c, -s);
            long long idxs = (base * 32LL) % NF;
            sincospif(2.0f * (float)idxs / (float)NF, &s, &c);
            st[u] = make_float2(c, -s);
            acc[u] = make_float2(0.f, 0.f);
        }
#pragma unroll 4
        for (int it = 0; it < 64; it++) {
            float v = s_q[lane + 32 * it];
#pragma unroll
            for (int u = 0; u < 4; u++) {
                acc[u].x = fmaf(v, ph[u].x, acc[u].x);
                acc[u].y = fmaf(v, ph[u].y, acc[u].y);
                ph[u] = cmul(ph[u], st[u]);
            }
        }
#pragma unroll
        for (int u = 0; u < 4; u++) {
            for (int off = 16; off; off >>= 1) {
                acc[u].x += __shfl_down_sync(0xffffffffu, acc[u].x, off);
                acc[u].y += __shfl_down_sync(0xffffffffu, acc[u].y, off);
            }
        }
        if (lane == 0) {
#pragma unroll
            for (int u = 0; u < 4; u++) {
                int j = jbase + 4 * warp + u;
                long long idxU = (2LL * j * M0C + (long long)j * j) % (2LL * NF);
                float s, c;
                sincospif((float)idxU / (float)NF, &s, &c);
                int slot = 512 * (j >> 9) + 8 * (j & 63) + ((j >> 6) & 7);
                g_UH[q * 2048 + slot] = cmul(acc[u], make_float2(c, s));
            }
        }
    }
}

// ================= main kernel: 64x64 CT, affine-immediate addressing =================
// smem: tw 512 | Z 2337 | E1 4670 | E2 4670 | t512 64 | t64 8 | t256 32 | t32 4 = 12297 f2
#define SMEM_MAIN_F2 (512 + 2337 + 4670 + 4670 + 64 + 8 + 32 + 4)

__global__ __launch_bounds__(512, 2) void k_main(float* __restrict__ out) {
    float2* s_tw   = smem_c;            // 512
    float2* s_Z    = smem_c + 512;      // 2337 (padded 2048 + dup slot 2336)
    float2* sE1    = smem_c + 2849;     // 4670
    float2* sE2    = sE1 + 4670;        // 4670
    float2* s_t512 = sE2 + 4670;        // 64
    float2* s_t64  = s_t512 + 64;       // 8
    float2* s_t256 = s_t64 + 8;         // 32
    float2* s_t32  = s_t256 + 32;       // 4

    int b = blockIdx.x / 9, c = blockIdx.x % 9;
    int t = threadIdx.x;

    s_tw[t] = g_tw[t & 511];
    if (t < 64) s_t512[t] = g_tw[8 * t];
    if (t < 8)  s_t64[t]  = g_tw[64 * t];
    if (t < 32) s_t256[t] = g_tw[16 * t];
    if (t < 4)  s_t32[t]  = g_tw[128 * t];
    __syncthreads();

    const float* Ar = g_A + (c * BATCH + b) * T;
    const float* Ai = g_B + (c * BATCH + b) * T;

    // ===== phase 0: packed 2048-point FFT (256 active threads, ping-pong E1/E2) =====
    float2 a[8];
    if (t < 256) {
#pragma unroll
        for (int j = 0; j < 8; j++) {
            int i = t + 256 * j;
            a[j] = make_float2(Ai[i], Ar[i]);   // z = Xir + i*Xr
        }
        fwd8(a); twid_fwd(a, s_tw[2 * t]);
#pragma unroll
        for (int r = 0; r < 8; r++) sE1[PAD(256 * r + t)] = a[r];
    }
    __syncthreads();
    if (t < 256) {  // stage2: S=256 q=32  E1->E2
        int pb = 256 * (t >> 5), pk = t & 31;
#pragma unroll
        for (int j = 0; j < 8; j++) a[j] = sE1[PAD(pb + pk + 32 * j)];
        fwd8(a); twid_fwd(a, s_t256[pk]);
#pragma unroll
        for (int r = 0; r < 8; r++) sE2[PAD(pb + 32 * r + pk)] = a[r];
    }
    __syncthreads();
    if (t < 256) {  // stage3: S=32 q=4  E2->E1
        int pb = 32 * (t >> 2), pk = t & 3;
#pragma unroll
        for (int j = 0; j < 8; j++) a[j] = sE2[PAD(pb + pk + 4 * j)];
        fwd8(a); twid_fwd(a, s_t32[pk]);
#pragma unroll
        for (int r = 0; r < 8; r++) sE1[PAD(pb + 4 * r + pk)] = a[r];
    }
    __syncthreads();
    if (t < 256) {  // stage4: radix-4 x2, unscramble  E1->s_Z (padded)
#pragma unroll
        for (int h = 0; h < 2; h++) {
            int B = 2 * t + h;
            float2 b4[4];
#pragma unroll
            for (int j = 0; j < 4; j++) b4[j] = sE1[PAD(4 * B + j)];
            float2 e0 = cadd(b4[0], b4[2]), e1 = csub(b4[0], b4[2]);
            float2 o0 = cadd(b4[1], b4[3]), o1 = csub(b4[1], b4[3]);
            float2 y0 = cadd(e0, o0), y2 = csub(e0, o0);
            float2 y1 = make_float2(e1.x + o1.y, e1.y - o1.x);
            float2 y3 = make_float2(e1.x - o1.y, e1.y + o1.x);
            int f = (B >> 6) + 8 * ((B >> 3) & 7) + 64 * (B & 7);
            s_Z[PAD(f)] = y0; s_Z[PAD(f + 512)] = y1;
            s_Z[PAD(f + 1024)] = y2; s_Z[PAD(f + 1536)] = y3;
            if (B == 0) s_Z[2336] = y0;   // duplicate Z[0] at affine slot PAD(2048)
        }
    }
    __syncthreads();

    // ===== chirp rounds (64x64 Cooley-Tukey, affine bases) =====
    float2 c1r[4], Pr[4];
    const float sc = 1.0f / (4096.0f * (float)NF);
    const int lam = t & 7;     // lane within 8-group
    const int S   = t >> 3;    // sequence index (step1: j) / k1 (middle)
    const float2 w64l = s_t64[lam];
    const float2 wS0  = s_tw[S * lam];   // w4096^{S*lam}
    const float2 wS1  = s_tw[8 * S];     // w4096^{8S}
    const int B1 = PAD(64 * lam + S);             // slot base for (512r + 64lam + S)
    const int B2 = 73 * S + lam;                  // slot base for (64S + 8r + lam)
    const int BM = PAD(512 - 64 * lam - S);       // mirror base
    const float2* Wp = g_W + 64 * S + 8 * lam;

#pragma unroll
    for (int s = 0; s < 4; s++) {
        bool useIr = (s == 0 || s == 2);
        const float2* UH = g_UH + s * 2048 + t;

        // ---- step1: gen u (half-zero), warp-local DFT64 over i, outer twiddle ----
#pragma unroll
        for (int r = 0; r < 4; r++) {
            float2 Zj = s_Z[B1 + 584 * r];
            float2 Zm = s_Z[BM + 584 * (3 - r)];
            float2 X = useIr
                ? make_float2(0.5f * (Zj.x + Zm.x), 0.5f * (Zj.y - Zm.y))
                : make_float2(0.5f * (Zj.y + Zm.y), 0.5f * (Zm.x - Zj.x));
            a[r] = cmul(X, UH[512 * r]);
        }
        fwd8h(a); twid_fwd(a, w64l); transpose8(a, lam); fwd8(a);
        {
#pragma unroll
            for (int r = 0; r < 8; r++) a[r] = cmul(a[r], wS0);
            twid_fwd(a, wS1);
        }
#pragma unroll
        for (int r = 0; r < 8; r++) sE1[B1 + 584 * r] = a[r];
        __syncthreads();

        // ---- middle: DFT64 over j + W + invDFT64 + conj outer twiddle (registers) ----
#pragma unroll
        for (int r = 0; r < 8; r++) a[r] = sE1[B2 + 9 * r];
        fwd64(a, lam, s_t64);
        {
            const float4* W4 = (const float4*)Wp;
            float4 w = W4[0];
            a[0] = cmul(a[0], make_float2(w.x, w.y)); a[1] = cmul(a[1], make_float2(w.z, w.w));
            w = W4[1];
            a[2] = cmul(a[2], make_float2(w.x, w.y)); a[3] = cmul(a[3], make_float2(w.z, w.w));
            w = W4[2];
            a[4] = cmul(a[4], make_float2(w.x, w.y)); a[5] = cmul(a[5], make_float2(w.z, w.w));
            w = W4[3];
            a[6] = cmul(a[6], make_float2(w.x, w.y)); a[7] = cmul(a[7], make_float2(w.z, w.w));
        }
        inv64(a, lam, s_t64);
        {
#pragma unroll
            for (int r = 0; r < 8; r++) a[r] = cmulc(a[r], wS0);
            twid_inv(a, wS1);
        }
#pragma unroll
        for (int r = 0; r < 8; r++) sE2[B1 + 584 * r] = a[r];
        __syncthreads();

        // ---- step1': inverse DFT64 over k1, keep positions i<32 (r=0..3) ----
#pragma unroll
        for (int r = 0; r < 8; r++) a[r] = sE2[B2 + 9 * r];
        inv64(a, lam, s_t64);
#pragma unroll
        for (int j = 0; j < 4; j++) {
            float2 v = make_float2(a[j].x * sc, a[j].y * sc);
            if (s == 0) c1r[j] = v;
            else if (s == 1) Pr[j] = cmul(c1r[j], v);
            else if (s == 2) c1r[j] = v;
            else {
                float2 p = cmul(c1r[j], v);
                Pr[j].x += p.x; Pr[j].y += p.y;
            }
        }
        // no extra sync: next round's step1 writes sE1; its readers finished
        // before the sync after the middle store above
    }

    // ===== permute results to m = t + 512j layout (coalesced psi/out) =====
    // sE1 is free: its last readers (round-3 middle) finished before round-3 mid-sync.
#pragma unroll
    for (int j = 0; j < 4; j++) sE1[B1 + 584 * j] = Pr[j];
    __syncthreads();
    {
        const int BT = PAD(t);
#pragma unroll
        for (int j = 0; j < 4; j++) {
            float2 p = sE1[BT + 584 * j];
            int m = t + 512 * j;
            float2 psi = g_psi[m];
            out[(b * T + m) * 9 + c] = p.x * psi.x - p.y * psi.y;
        }
    }
}

// ---------------- launch ----------------
extern "C" void kernel_launch(void* const* d_in, const int* in_sizes, int n_in,
                              void* d_out, int out_size) {
    const float* xd = (const float*)d_in[0];
    const float* A1 = (const float*)d_in[1];
    const float* A2 = (const float*)d_in[2];
    FnnW wf  = {(const float*)d_in[3],  (const float*)d_in[4],  (const float*)d_in[5],  (const float*)d_in[6]};
    FnnW wg  = {(const float*)d_in[7],  (const float*)d_in[8],  (const float*)d_in[9],  (const float*)d_in[10]};
    FnnW wfp = {(const float*)d_in[11], (const float*)d_in[12], (const float*)d_in[13], (const float*)d_in[14]};
    FnnW wgp = {(const float*)d_in[15], (const float*)d_in[16], (const float*)d_in[17], (const float*)d_in[18]};
    float* out = (float*)d_out;

    int smem_pre  = (512 + 4670 + 8 + 64) * sizeof(float2);    // ~42 KB (W role largest)
    int smem_main = SMEM_MAIN_F2 * sizeof(float2);             // 98,376 B
    cudaFuncSetAttribute(k_pre,  cudaFuncAttributeMaxDynamicSharedMemorySize, smem_pre);
    cudaFuncSetAttribute(k_main, cudaFuncAttributeMaxDynamicSharedMemorySize, smem_main);

    k_pre<<<197, 512, smem_pre>>>(xd, A1, A2, wf, wg, wfp, wgp);
    k_main<<<BATCH * 9, 512, smem_main>>>(out);
}